// round 3
// baseline (speedup 1.0000x reference)
#include <cuda_runtime.h>
#include <cstdint>

// PatchNeighborSearcher: B=8, H=W=16 (P=256), L=64, C=64.
// out[b, p, l*8+n, c] = in[b, neighbor_p(n), l, c] if in-bounds else 0.
//
// 256-bit (v8.f32) global accesses, one thread per (b,p,l,c8) chunk of 8 floats,
// producing all 8 neighbor outputs (8 loads + 8 stores of 32B each).
//
// In 8-float units: input idx = tid = (b<<17)|(p<<9)|(l<<3)|c8.
// Neighbor (dy,dx): input idx = tid + ((dy*16+dx)<<9)  [compile-time consts].
// Output idx = (b<<20)|(p<<12)|(l<<6)|(n<<3)|c8 = ((tid&~7)<<3)|(n<<3)|(tid&7).

__device__ __forceinline__ void ldg256_cond(float v[8], const float* a, int pred)
{
    asm("{\n\t"
        ".reg .pred p;\n\t"
        "setp.ne.s32 p, %9, 0;\n\t"
        "mov.b32 %0, 0; mov.b32 %1, 0; mov.b32 %2, 0; mov.b32 %3, 0;\n\t"
        "mov.b32 %4, 0; mov.b32 %5, 0; mov.b32 %6, 0; mov.b32 %7, 0;\n\t"
        "@p ld.global.nc.v8.f32 {%0,%1,%2,%3,%4,%5,%6,%7}, [%8];\n\t"
        "}"
        : "=f"(v[0]), "=f"(v[1]), "=f"(v[2]), "=f"(v[3]),
          "=f"(v[4]), "=f"(v[5]), "=f"(v[6]), "=f"(v[7])
        : "l"(a), "r"(pred));
}

__device__ __forceinline__ void stg256_cs(float* a, const float v[8])
{
    asm volatile(
        "st.global.cs.v8.f32 [%0], {%1,%2,%3,%4,%5,%6,%7,%8};"
        :: "l"(a),
           "f"(v[0]), "f"(v[1]), "f"(v[2]), "f"(v[3]),
           "f"(v[4]), "f"(v[5]), "f"(v[6]), "f"(v[7])
        : "memory");
}

__global__ void __launch_bounds__(256) patch_neighbor_kernel(
    const float* __restrict__ in, float* __restrict__ out)
{
    int tid = blockIdx.x * blockDim.x + threadIdx.x;   // 1,048,576 threads

    int h = (tid >> 13) & 15;
    int w = (tid >> 9) & 15;

    int hm = (h > 0);
    int hp = (h < 15);
    int wm = (w > 0);
    int wp = (w < 15);

    // neighbor order: (-1,-1)(-1,0)(-1,1)(0,-1)(0,1)(1,-1)(1,0)(1,1)
    int valid[8] = { hm & wm, hm, hm & wp,
                     wm,          wp,
                     hp & wm, hp, hp & wp };

    // input offset per neighbor, in 8-float (32B) units: (dy*16 + dx) << 9
    constexpr int OFF[8] = {
        (-17) << 9, (-16) << 9, (-15) << 9,
        ( -1) << 9,              (  1) << 9,
        ( 15) << 9, ( 16) << 9, ( 17) << 9
    };

    const float* base = in + ((long)tid << 3);   // float ptr; tid in 8-float units

    float v[8][8];
    #pragma unroll
    for (int n = 0; n < 8; n++) {
        ldg256_cond(v[n], base + ((long)OFF[n] << 3), valid[n]);
    }

    long obase = ((long)((tid & ~7) << 3) | (tid & 7)) << 3;   // float index
    #pragma unroll
    for (int n = 0; n < 8; n++) {
        stg256_cs(out + obase + ((long)n << 6), v[n]);
    }
}

extern "C" void kernel_launch(void* const* d_in, const int* in_sizes, int n_in,
                              void* d_out, int out_size)
{
    const float* in = (const float*)d_in[0];
    float* out = (float*)d_out;

    int threads_total = out_size / 64;   // out_size/8 floats-per-unit /8 neighbors
    int block = 256;
    int grid = (threads_total + block - 1) / block;
    patch_neighbor_kernel<<<grid, block>>>(in, out);
}

// round 4
// speedup vs baseline: 1.0381x; 1.0381x over previous
#include <cuda_runtime.h>
#include <cstdint>

// PatchNeighborSearcher: B=8, H=W=16 (P=256), L=64, C=64.
// out[b, p, l*8+n, c] = in[b, neighbor_p(n), l, c] if in-bounds else 0.
//
// L1-reuse tiling: thread id decodes as (b, l, h, w, c4) with block = 16w x 16c4
// at fixed (b, l, h). Adjacent-w threads in the same block read overlapping
// neighbor rows -> dedup in L1 instead of hammering L2 8x.
//
// Input  float4 idx: (b<<18)|(h<<14)|(w<<10)|(l<<4)|c4
// Output float4 idx: (b<<21)|(h<<17)|(w<<13)|(l<<7)|(n<<4)|c4

__global__ void __launch_bounds__(256) patch_neighbor_kernel(
    const float4* __restrict__ in, float4* __restrict__ out)
{
    int tid = blockIdx.x * blockDim.x + threadIdx.x;   // 2,097,152 threads

    int c4 = tid & 15;
    int w  = (tid >> 4) & 15;
    int h  = (tid >> 8) & 15;
    int l  = (tid >> 12) & 63;
    int b  = tid >> 18;

    int hm = (h > 0);
    int hp = (h < 15);
    int wm = (w > 0);
    int wp = (w < 15);

    // neighbor order: (-1,-1)(-1,0)(-1,1)(0,-1)(0,1)(1,-1)(1,0)(1,1)
    int valid[8] = { hm & wm, hm, hm & wp,
                     wm,          wp,
                     hp & wm, hp, hp & wp };

    // neighbor offset in float4 units: (dy*16 + dx) << 10
    constexpr int OFF[8] = {
        (-17) << 10, (-16) << 10, (-15) << 10,
        ( -1) << 10,               (  1) << 10,
        ( 15) << 10, ( 16) << 10, ( 17) << 10
    };

    int ibase = (b << 18) | (h << 14) | (w << 10) | (l << 4) | c4;
    int obase = (b << 21) | (h << 17) | (w << 13) | (l << 7) | c4;

    const float4 zero = make_float4(0.f, 0.f, 0.f, 0.f);
    float4 v[8];

    #pragma unroll
    for (int n = 0; n < 8; n++) {
        v[n] = valid[n] ? __ldg(&in[ibase + OFF[n]]) : zero;
    }

    #pragma unroll
    for (int n = 0; n < 8; n++) {
        __stcs(&out[obase + (n << 4)], v[n]);
    }
}

extern "C" void kernel_launch(void* const* d_in, const int* in_sizes, int n_in,
                              void* d_out, int out_size)
{
    const float4* in = (const float4*)d_in[0];
    float4* out = (float4*)d_out;

    int threads_total = (out_size / 4) / 8;   // 2,097,152
    int block = 256;
    int grid = (threads_total + block - 1) / block;
    patch_neighbor_kernel<<<grid, block>>>(in, out);
}